// round 1
// baseline (speedup 1.0000x reference)
#include <cuda_runtime.h>
#include <math.h>
#include <float.h>

#ifndef M_PI
#define M_PI 3.14159265358979323846
#endif

// Problem constants
// B=1, C_IN=32, D_OUT=32, P=2048, N=10, A=12

// ---------------- scratch (__device__ globals; no allocations allowed) ----
__device__ float g_VS[36];                 // [12][3]
__device__ float g_SYMR[45];               // [5][3][3]
__device__ float g_VER[108];               // [12][3][3]  VERTICER[r][i][j]
__device__ float g_KDNRO[32 * 12 * 12 * 3];// [d][k][r][i]
__device__ float g_W2[416 * 96];           // [d*13+k][c*3+j]  (Wfull reorganized)
__device__ float g_BIASF[416];             // [d*13+k]
__device__ float g_FMS[2048 * 96];         // [p][c*3+i]
__device__ float g_KA[32 * 13 * 2048 * 12];// [(d*13+k)][p][r]  (40.9 MB)

// ---------------- kernel A: base icosa constants (double precision) -------
__global__ void k_init_base() {
    if (threadIdx.x != 0 || blockIdx.x != 0) return;
    const double phi = (1.0 + sqrt(5.0)) * 0.5;
    double v[12][3];
    int idx = 0;
    double as_[2] = {1.0, -1.0};
    double bs_[2] = {phi, -phi};
    for (int ia = 0; ia < 2; ia++)
        for (int ib = 0; ib < 2; ib++) {
            double a = as_[ia], b = bs_[ib];
            v[idx][0] = 0.0; v[idx][1] = a;   v[idx][2] = b;   idx++;
            v[idx][0] = a;   v[idx][1] = b;   v[idx][2] = 0.0; idx++;
            v[idx][0] = b;   v[idx][1] = 0.0; v[idx][2] = a;   idx++;
        }
    for (int i = 0; i < 12; i++) {
        double n = sqrt(v[i][0]*v[i][0] + v[i][1]*v[i][1] + v[i][2]*v[i][2]);
        for (int j = 0; j < 3; j++) { v[i][j] /= n; g_VS[i*3+j] = (float)v[i][j]; }
    }
    for (int m = 0; m < 5; m++) {
        double t = 2.0 * M_PI * (double)m / 5.0;
        double ct = cos(t), st = sin(t);
        double R[3][3] = {{ct, -st, 0.0}, {st, ct, 0.0}, {0.0, 0.0, 1.0}};
        for (int i = 0; i < 3; i++)
            for (int j = 0; j < 3; j++)
                g_SYMR[m*9 + i*3 + j] = (float)R[i][j];
    }
    for (int r = 0; r < 12; r++) {
        double ux = v[r][0], uy = v[r][1], uz = v[r][2];
        double c = uz;
        double axx = -uy, axy = ux;           // cross(z, u)
        double s = sqrt(axx*axx + axy*axy);
        double R[3][3];
        if (s < 1e-9) {
            for (int i = 0; i < 3; i++) for (int j = 0; j < 3; j++) R[i][j] = 0.0;
            R[0][0] = 1.0;
            R[1][1] = (c > 0) ? 1.0 : -1.0;
            R[2][2] = (c > 0) ? 1.0 : -1.0;
        } else {
            double kx = axx / s, ky = axy / s, kz = 0.0;
            double K[3][3] = {{0, -kz, ky}, {kz, 0, -kx}, {-ky, kx, 0}};
            double KK[3][3];
            for (int i = 0; i < 3; i++)
                for (int j = 0; j < 3; j++) {
                    double acc = 0.0;
                    for (int q = 0; q < 3; q++) acc += K[i][q]*K[q][j];
                    KK[i][j] = acc;
                }
            for (int i = 0; i < 3; i++)
                for (int j = 0; j < 3; j++)
                    R[i][j] = (i == j ? 1.0 : 0.0) + s*K[i][j] + (1.0 - c)*KK[i][j];
        }
        for (int i = 0; i < 3; i++)
            for (int j = 0; j < 3; j++)
                g_VER[r*9 + i*3 + j] = (float)R[i][j];
    }
}

// ---------------- kernel B: input-dependent weight prep -------------------
// tasks: [0,4608) KDN_RO per (d,k,r); [4608,17920) W2 per (dk,c); [17920,18336) bias
__global__ void k_init_weights(const float* __restrict__ W,
                               const float* __restrict__ bias,
                               const float* __restrict__ dirs) {
    int t = blockIdx.x * blockDim.x + threadIdx.x;
    if (t < 4608) {
        int d = t / 144, k = (t / 12) % 12, r = t % 12;
        float vv[3];
        if (k == 0)      { vv[0] = 0.f; vv[1] = 0.f; vv[2] = 1.f; }
        else if (k == 1) { vv[0] = 0.f; vv[1] = 0.f; vv[2] = -1.f; }
        else {
            int kk = (k - 2) / 5, m = (k - 2) % 5;
            float d0 = dirs[d*6 + kk*3 + 0];
            float d1 = dirs[d*6 + kk*3 + 1];
            float d2 = dirs[d*6 + kk*3 + 2];
            float nrm = sqrtf(d0*d0 + d1*d1 + d2*d2);
            float inv = 1.f / fmaxf(nrm, 1e-12f);
            d0 *= inv; d1 *= inv; d2 *= inv;
            for (int i = 0; i < 3; i++)
                vv[i] = g_SYMR[m*9+i*3+0]*d0 + g_SYMR[m*9+i*3+1]*d1 + g_SYMR[m*9+i*3+2]*d2;
        }
        for (int i = 0; i < 3; i++) {
            float o = g_VER[r*9+i*3+0]*vv[0] + g_VER[r*9+i*3+1]*vv[1] + g_VER[r*9+i*3+2]*vv[2];
            g_KDNRO[((d*12 + k)*12 + r)*3 + i] = o;
        }
    } else if (t < 4608 + 13312) {
        int id = t - 4608;
        int dk = id / 32, c = id % 32;
        int d = dk / 13, k = dk % 13;
        const float* wr = W + (d*32 + c)*9;
        float wf[3];
        if (k == 0)       { wf[0] = 0.f; wf[1] = 0.f; wf[2] = wr[0]; }
        else if (k == 1)  { wf[0] = 0.f; wf[1] = 0.f; wf[2] = -wr[1]; }
        else if (k == 12) { wf[0] = 0.f; wf[1] = 0.f; wf[2] = wr[8]; }
        else {
            int kk = (k - 2) / 5, m = (k - 2) % 5;
            float w0 = wr[2 + kk*3 + 0], w1 = wr[2 + kk*3 + 1], w2 = wr[2 + kk*3 + 2];
            for (int i = 0; i < 3; i++)
                wf[i] = g_SYMR[m*9+i*3+0]*w0 + g_SYMR[m*9+i*3+1]*w1 + g_SYMR[m*9+i*3+2]*w2;
        }
        g_W2[dk*96 + c*3 + 0] = wf[0];
        g_W2[dk*96 + c*3 + 1] = wf[1];
        g_W2[dk*96 + c*3 + 2] = wf[2];
    } else if (t < 4608 + 13312 + 416) {
        int dk = t - (4608 + 13312);
        int d = dk / 13, k = dk % 13;
        int col = (k == 0) ? 0 : (k == 1) ? 1 : (k <= 6) ? 2 : (k <= 11) ? 3 : 4;
        g_BIASF[dk] = bias[d*5 + col];
    }
}

// ---------------- kernel C: attention softmax + fm ------------------------
// one block per point p; 384 threads = (a=12) x (c=32)
__global__ void __launch_bounds__(384) k_fm(const float* __restrict__ fmap,
                                            const float* __restrict__ fcw,
                                            float* __restrict__ fm_out) {
    __shared__ float Xs[384];
    __shared__ float FCs[1024];
    __shared__ float Ls[384];
    __shared__ float Es[384];
    __shared__ float Ys[384];
    int p = blockIdx.x, tid = threadIdx.x;
    int a = tid >> 5, c = tid & 31;
    Xs[tid] = fmap[(c*2048 + p)*12 + a];     // X[a][c]
    for (int i = tid; i < 1024; i += 384) FCs[i] = fcw[i];
    __syncthreads();
    float l = 0.f;
#pragma unroll
    for (int cc = 0; cc < 32; cc++) l += Xs[a*32 + cc] * FCs[c*32 + cc];
    Ls[tid] = l;
    __syncthreads();
    float mx = -FLT_MAX;
#pragma unroll
    for (int aa = 0; aa < 12; aa++) mx = fmaxf(mx, Ls[aa*32 + c]);
    float e = expf(l - mx);
    Es[tid] = e;
    __syncthreads();
    float s = 0.f;
#pragma unroll
    for (int aa = 0; aa < 12; aa++) s += Es[aa*32 + c];
    Ys[tid] = (e / s) * Xs[tid];
    __syncthreads();
    if (tid < 96) {
        int cc = tid / 3, r = tid % 3;
        float acc = 0.f;
#pragma unroll
        for (int aa = 0; aa < 12; aa++) acc += g_VS[aa*3 + r] * Ys[aa*32 + cc];
        g_FMS[p*96 + tid] = acc;
        fm_out[(cc*2048 + p)*3 + r] = acc;   // fm output region
    }
}

// ---------------- kernel D: ka[d,k,p,r] via factored rotation --------------
// 416 threads = one per (d,k); W row lives in registers, reused across 8 p
__global__ void __launch_bounds__(416, 1) k_ka() {
    __shared__ float fms[768];
    __shared__ float ver[108];
    int tid = threadIdx.x;
    float w[96];
#pragma unroll
    for (int q = 0; q < 96; q++) w[q] = g_W2[tid*96 + q];
    float bv = g_BIASF[tid];
    if (tid < 108) ver[tid] = g_VER[tid];
    int p0 = blockIdx.x * 8;
    for (int i = tid; i < 768; i += 416) fms[i] = g_FMS[p0*96 + i];
    __syncthreads();
#pragma unroll 1
    for (int pp = 0; pp < 8; pp++) {
        float G[9];
#pragma unroll
        for (int q = 0; q < 9; q++) G[q] = 0.f;
#pragma unroll
        for (int c = 0; c < 32; c++) {
            float f0 = fms[pp*96 + c*3 + 0];
            float f1 = fms[pp*96 + c*3 + 1];
            float f2 = fms[pp*96 + c*3 + 2];
#pragma unroll
            for (int j = 0; j < 3; j++) {
                float wv = w[c*3 + j];
                G[j*3+0] += wv*f0; G[j*3+1] += wv*f1; G[j*3+2] += wv*f2;
            }
        }
        int p = p0 + pp;
        float o12[12];
#pragma unroll
        for (int r = 0; r < 12; r++) {
            float s = bv;
#pragma unroll
            for (int i = 0; i < 3; i++)
#pragma unroll
                for (int j = 0; j < 3; j++)
                    s += ver[r*9 + i*3 + j] * G[j*3 + i];
            o12[r] = s;
        }
        float4* dst = (float4*)&g_KA[((size_t)tid*2048 + p)*12];
        dst[0] = make_float4(o12[0], o12[1], o12[2],  o12[3]);
        dst[1] = make_float4(o12[4], o12[5], o12[6],  o12[7]);
        dst[2] = make_float4(o12[8], o12[9], o12[10], o12[11]);
    }
}

// ---------------- kernel E: theta + gather + max_n + sum_k + center -------
// block = 4 points x 96 (d,rg) threads; rg covers 4 of the 12 r values (float4)
__global__ void __launch_bounds__(384) k_final(const int* __restrict__ nbr,
                                               const float* __restrict__ verts,
                                               float* __restrict__ out) {
    __shared__ float ndn[4][10][3];
    __shared__ int qidx[4][10];
    int tid = threadIdx.x;
    if (tid < 40) {
        int pp2 = tid / 10, n = tid % 10;
        int p2 = blockIdx.x*4 + pp2;
        int q = nbr[p2*10 + n];
        qidx[pp2][n] = q;
        float dx = verts[q*3+0] - verts[p2*3+0];
        float dy = verts[q*3+1] - verts[p2*3+1];
        float dz = verts[q*3+2] - verts[p2*3+2];
        float nrm = sqrtf(dx*dx + dy*dy + dz*dz);
        float inv = 1.f / fmaxf(nrm, 1e-12f);
        ndn[pp2][n][0] = dx*inv; ndn[pp2][n][1] = dy*inv; ndn[pp2][n][2] = dz*inv;
    }
    __syncthreads();
    int pp = tid / 96;
    int u = tid % 96;
    int d = u / 3, rg = u % 3;
    int p = blockIdx.x*4 + pp;

    const float4* cen = (const float4*)&g_KA[(((size_t)d*13 + 12)*2048 + p)*12];
    float4 a4 = cen[rg];
    float acc0 = a4.x, acc1 = a4.y, acc2 = a4.z, acc3 = a4.w;

#pragma unroll 1
    for (int k = 0; k < 12; k++) {
        const float4* kro = (const float4*)&g_KDNRO[((d*12 + k)*12 + rg*4)*3];
        float4 kA = __ldg(kro + 0);
        float4 kB = __ldg(kro + 1);
        float4 kC = __ldg(kro + 2);
        const float* kabase = &g_KA[(((size_t)d*13 + k)*2048) * 12];
        float m0 = 0.f, m1 = 0.f, m2 = 0.f, m3 = 0.f;
#pragma unroll
        for (int n = 0; n < 10; n++) {
            float nx = ndn[pp][n][0], ny = ndn[pp][n][1], nz = ndn[pp][n][2];
            float t0 = fmaxf(kA.x*nx + kA.y*ny + kA.z*nz, 0.f);
            float t1 = fmaxf(kA.w*nx + kB.x*ny + kB.y*nz, 0.f);
            float t2 = fmaxf(kB.z*nx + kB.w*ny + kC.x*nz, 0.f);
            float t3 = fmaxf(kC.y*nx + kC.z*ny + kC.w*nz, 0.f);
            int q = qidx[pp][n];
            float4 kav = *(const float4*)&kabase[(size_t)q*12 + rg*4];
            float v0 = t0*kav.x, v1 = t1*kav.y, v2 = t2*kav.z, v3 = t3*kav.w;
            if (n == 0) { m0 = v0; m1 = v1; m2 = v2; m3 = v3; }
            else {
                m0 = fmaxf(m0, v0); m1 = fmaxf(m1, v1);
                m2 = fmaxf(m2, v2); m3 = fmaxf(m3, v3);
            }
        }
        acc0 += m0; acc1 += m1; acc2 += m2; acc3 += m3;
    }
    float4* o = (float4*)&out[((size_t)d*2048 + p)*12 + rg*4];
    *o = make_float4(acc0, acc1, acc2, acc3);
}

// ---------------- launch ----------------------------------------------------
extern "C" void kernel_launch(void* const* d_in, const int* in_sizes, int n_in,
                              void* d_out, int out_size) {
    const int*   nbr   = (const int*)d_in[0];   // (1,2048,10)
    const float* verts = (const float*)d_in[1]; // (1,2048,3)
    const float* fmap  = (const float*)d_in[2]; // (1,32,2048,12)
    const float* W     = (const float*)d_in[3]; // (32,32,9)
    const float* bias  = (const float*)d_in[4]; // (32,5)
    const float* dirs  = (const float*)d_in[5]; // (32,2,3)
    const float* fcw   = (const float*)d_in[6]; // (32,32)
    float* out    = (float*)d_out;              // (1,32,2048,12)
    float* fm_out = out + 32*2048*12;           // (1,32,2048,3)

    k_init_base<<<1, 32>>>();
    k_init_weights<<<72, 256>>>(W, bias, dirs);
    k_fm<<<2048, 384>>>(fmap, fcw, fm_out);
    k_ka<<<256, 416>>>();
    k_final<<<512, 384>>>(nbr, verts, out);
}

// round 2
// speedup vs baseline: 1.9472x; 1.9472x over previous
#include <cuda_runtime.h>
#include <cuda_fp16.h>
#include <math.h>
#include <float.h>

#ifndef M_PI
#define M_PI 3.14159265358979323846
#endif

// B=1, C_IN=32, D_OUT=32, P=2048, N=10, A=12

// ---------------- device scratch ------------------------------------------
// g_ICO layout: VS[36] | SYMR[45] | VER[108]
__device__ float g_ICO[189];
__device__ float g_KDNRO[32 * 12 * 12 * 3];   // [d][k][r][i]
__device__ float g_W2[416 * 96];              // [dk][c*3+j]
__device__ float g_BIASF[416];                // [dk]
__device__ float g_FMS[2048 * 96];            // [p][c*3+i]
__device__ __half g_KAH[32 * 12 * 2048 * 12]; // [(d*12+k)][p][r]  fp16, 18.9MB
__device__ float g_CEN[32 * 2048 * 12];       // [d][p][r] center (k==12), fp32

#define VS_OFF   0
#define SYMR_OFF 36
#define VER_OFF  81

// ---------------- kernel B: input-dependent weight prep -------------------
__global__ void k_init_weights(const float* __restrict__ W,
                               const float* __restrict__ bias,
                               const float* __restrict__ dirs) {
    int t = blockIdx.x * blockDim.x + threadIdx.x;
    const float* SYMR = g_ICO + SYMR_OFF;
    const float* VER  = g_ICO + VER_OFF;
    if (t < 4608) {
        int d = t / 144, k = (t / 12) % 12, r = t % 12;
        float vv[3];
        if (k == 0)      { vv[0] = 0.f; vv[1] = 0.f; vv[2] = 1.f; }
        else if (k == 1) { vv[0] = 0.f; vv[1] = 0.f; vv[2] = -1.f; }
        else {
            int kk = (k - 2) / 5, m = (k - 2) % 5;
            float d0 = dirs[d*6 + kk*3 + 0];
            float d1 = dirs[d*6 + kk*3 + 1];
            float d2 = dirs[d*6 + kk*3 + 2];
            float nrm = sqrtf(d0*d0 + d1*d1 + d2*d2);
            float inv = 1.f / fmaxf(nrm, 1e-12f);
            d0 *= inv; d1 *= inv; d2 *= inv;
            for (int i = 0; i < 3; i++)
                vv[i] = SYMR[m*9+i*3+0]*d0 + SYMR[m*9+i*3+1]*d1 + SYMR[m*9+i*3+2]*d2;
        }
        for (int i = 0; i < 3; i++) {
            float o = VER[r*9+i*3+0]*vv[0] + VER[r*9+i*3+1]*vv[1] + VER[r*9+i*3+2]*vv[2];
            g_KDNRO[((d*12 + k)*12 + r)*3 + i] = o;
        }
    } else if (t < 4608 + 13312) {
        int id = t - 4608;
        int dk = id / 32, c = id % 32;
        int d = dk / 13, k = dk % 13;
        const float* wr = W + (d*32 + c)*9;
        float wf[3];
        if (k == 0)       { wf[0] = 0.f; wf[1] = 0.f; wf[2] = wr[0]; }
        else if (k == 1)  { wf[0] = 0.f; wf[1] = 0.f; wf[2] = -wr[1]; }
        else if (k == 12) { wf[0] = 0.f; wf[1] = 0.f; wf[2] = wr[8]; }
        else {
            int kk = (k - 2) / 5, m = (k - 2) % 5;
            float w0 = wr[2 + kk*3 + 0], w1 = wr[2 + kk*3 + 1], w2 = wr[2 + kk*3 + 2];
            for (int i = 0; i < 3; i++)
                wf[i] = SYMR[m*9+i*3+0]*w0 + SYMR[m*9+i*3+1]*w1 + SYMR[m*9+i*3+2]*w2;
        }
        g_W2[dk*96 + c*3 + 0] = wf[0];
        g_W2[dk*96 + c*3 + 1] = wf[1];
        g_W2[dk*96 + c*3 + 2] = wf[2];
    } else if (t < 4608 + 13312 + 416) {
        int dk = t - (4608 + 13312);
        int d = dk / 13, k = dk % 13;
        int col = (k == 0) ? 0 : (k == 1) ? 1 : (k <= 6) ? 2 : (k <= 11) ? 3 : 4;
        g_BIASF[dk] = bias[d*5 + col];
    }
}

// ---------------- kernel C: attention softmax + fm (warp per point) -------
__global__ void __launch_bounds__(256) k_fm(const float* __restrict__ fmap,
                                            const float* __restrict__ fcw,
                                            float* __restrict__ fm_out) {
    __shared__ float FCT[32*33];     // transposed fcw: FCT[cc*33+c] = fcw[c][cc]
    __shared__ float Xs[8][384];     // [warp][a*32+cc]
    __shared__ float VSs[36];
    int tid = threadIdx.x;
    for (int i = tid; i < 1024; i += 256) {
        int r = i >> 5, cc = i & 31;
        FCT[cc*33 + r] = fcw[i];
    }
    if (tid < 36) VSs[tid] = g_ICO[VS_OFF + tid];
    int w = tid >> 5, lane = tid & 31;
    int p = blockIdx.x*8 + w;
    const float* src = &fmap[((size_t)lane*2048 + p)*12];
#pragma unroll
    for (int a = 0; a < 12; a++) Xs[w][a*32+lane] = src[a];
    __syncthreads();

    float L[12];
#pragma unroll
    for (int a = 0; a < 12; a++) L[a] = 0.f;
#pragma unroll
    for (int cc = 0; cc < 32; cc++) {
        float fc = FCT[cc*33 + lane];
#pragma unroll
        for (int a = 0; a < 12; a++) L[a] += Xs[w][a*32+cc] * fc;
    }
    float mx = L[0];
#pragma unroll
    for (int a = 1; a < 12; a++) mx = fmaxf(mx, L[a]);
    float e[12], s = 0.f;
#pragma unroll
    for (int a = 0; a < 12; a++) { e[a] = expf(L[a] - mx); s += e[a]; }
    float inv = 1.f / s;
    float f0 = 0.f, f1 = 0.f, f2 = 0.f;
#pragma unroll
    for (int a = 0; a < 12; a++) {
        float y = e[a] * inv * Xs[w][a*32+lane];
        f0 += y * VSs[a*3+0];
        f1 += y * VSs[a*3+1];
        f2 += y * VSs[a*3+2];
    }
    g_FMS[p*96 + lane*3 + 0] = f0;
    g_FMS[p*96 + lane*3 + 1] = f1;
    g_FMS[p*96 + lane*3 + 2] = f2;
    fm_out[((size_t)lane*2048 + p)*3 + 0] = f0;
    fm_out[((size_t)lane*2048 + p)*3 + 1] = f1;
    fm_out[((size_t)lane*2048 + p)*3 + 2] = f2;
}

// ---------------- kernel D: ka via factored rotation (tiled) ---------------
// block 128 thr = 16 dk x 8 pslots; each thread: 1 dk x 4 points
__global__ void __launch_bounds__(128) k_ka() {
    __shared__ float Ws[16*97];
    __shared__ float Fs[32*97];
    __shared__ float ver[108];
    __shared__ float biasS[16];
    int tid = threadIdx.x;
    int dk0 = blockIdx.x * 16;
    int p0  = blockIdx.y * 32;
    for (int i = tid; i < 16*96; i += 128) {
        int row = i / 96, q = i % 96;
        Ws[row*97 + q] = g_W2[(dk0+row)*96 + q];
    }
    for (int i = tid; i < 32*96; i += 128) {
        int row = i / 96, q = i % 96;
        Fs[row*97 + q] = g_FMS[(p0+row)*96 + q];
    }
    if (tid < 108) ver[tid] = g_ICO[VER_OFF + tid];
    if (tid < 16)  biasS[tid] = g_BIASF[dk0 + tid];
    __syncthreads();

    int dkl = tid & 15;
    int ps  = tid >> 4;             // 0..7, covers 4 points each
    const float* wrow = &Ws[dkl*97];
    float G[4][9];
#pragma unroll
    for (int t = 0; t < 4; t++)
#pragma unroll
        for (int q = 0; q < 9; q++) G[t][q] = 0.f;

#pragma unroll 4
    for (int c = 0; c < 32; c++) {
        float w0 = wrow[c*3+0], w1 = wrow[c*3+1], w2 = wrow[c*3+2];
#pragma unroll
        for (int t = 0; t < 4; t++) {
            const float* fr = &Fs[(ps*4 + t)*97 + c*3];
            float f0 = fr[0], f1 = fr[1], f2 = fr[2];
            G[t][0] += w0*f0; G[t][1] += w0*f1; G[t][2] += w0*f2;
            G[t][3] += w1*f0; G[t][4] += w1*f1; G[t][5] += w1*f2;
            G[t][6] += w2*f0; G[t][7] += w2*f1; G[t][8] += w2*f2;
        }
    }

    int dk = dk0 + dkl;
    int d = dk / 13, k = dk % 13;
    float bv = biasS[dkl];
#pragma unroll
    for (int t = 0; t < 4; t++) {
        int p = p0 + ps*4 + t;
        float o[12];
#pragma unroll
        for (int r = 0; r < 12; r++) {
            float s = bv;
#pragma unroll
            for (int i = 0; i < 3; i++)
#pragma unroll
                for (int j = 0; j < 3; j++)
                    s += ver[r*9 + i*3 + j] * G[t][j*3 + i];
            o[r] = s;
        }
        if (k == 12) {
            float4* dst = (float4*)&g_CEN[((size_t)d*2048 + p)*12];
            dst[0] = make_float4(o[0], o[1], o[2],  o[3]);
            dst[1] = make_float4(o[4], o[5], o[6],  o[7]);
            dst[2] = make_float4(o[8], o[9], o[10], o[11]);
        } else {
            __half2* dst = (__half2*)&g_KAH[(((size_t)(d*12 + k))*2048 + p)*12];
#pragma unroll
            for (int h = 0; h < 6; h++)
                dst[h] = __floats2half2_rn(o[2*h], o[2*h+1]);
        }
    }
}

// ---------------- kernel E: theta + gather + max_n + sum_k + center -------
// block = 4 points x 96 (d,rg) threads
__global__ void __launch_bounds__(384) k_final(const int* __restrict__ nbr,
                                               const float* __restrict__ verts,
                                               float* __restrict__ out) {
    __shared__ float ndn[4][10][3];
    __shared__ int qidx[4][10];
    int tid = threadIdx.x;
    if (tid < 40) {
        int pp2 = tid / 10, n = tid % 10;
        int p2 = blockIdx.x*4 + pp2;
        int q = nbr[p2*10 + n];
        qidx[pp2][n] = q;
        float dx = verts[q*3+0] - verts[p2*3+0];
        float dy = verts[q*3+1] - verts[p2*3+1];
        float dz = verts[q*3+2] - verts[p2*3+2];
        float nrm = sqrtf(dx*dx + dy*dy + dz*dz);
        float inv = 1.f / fmaxf(nrm, 1e-12f);
        ndn[pp2][n][0] = dx*inv; ndn[pp2][n][1] = dy*inv; ndn[pp2][n][2] = dz*inv;
    }
    __syncthreads();
    int pp = tid / 96;
    int u  = tid % 96;
    int d  = u / 3, rg = u % 3;
    int p  = blockIdx.x*4 + pp;

    const float4* cen = (const float4*)&g_CEN[((size_t)d*2048 + p)*12];
    float4 a4 = cen[rg];
    float acc0 = a4.x, acc1 = a4.y, acc2 = a4.z, acc3 = a4.w;

#pragma unroll 1
    for (int k = 0; k < 12; k++) {
        const float4* kro = (const float4*)&g_KDNRO[((d*12 + k)*12 + rg*4)*3];
        float4 kA = __ldg(kro + 0);
        float4 kB = __ldg(kro + 1);
        float4 kC = __ldg(kro + 2);
        const __half* kabase = &g_KAH[((size_t)(d*12 + k))*2048*12];
        float m0 = 0.f, m1 = 0.f, m2 = 0.f, m3 = 0.f;
#pragma unroll
        for (int n = 0; n < 10; n++) {
            float nx = ndn[pp][n][0], ny = ndn[pp][n][1], nz = ndn[pp][n][2];
            float t0 = fmaxf(kA.x*nx + kA.y*ny + kA.z*nz, 0.f);
            float t1 = fmaxf(kA.w*nx + kB.x*ny + kB.y*nz, 0.f);
            float t2 = fmaxf(kB.z*nx + kB.w*ny + kC.x*nz, 0.f);
            float t3 = fmaxf(kC.y*nx + kC.z*ny + kC.w*nz, 0.f);
            int q = qidx[pp][n];
            uint2 raw = *(const uint2*)&kabase[(size_t)q*12 + rg*4];
            __half2 hA = *reinterpret_cast<__half2*>(&raw.x);
            __half2 hB = *reinterpret_cast<__half2*>(&raw.y);
            float2 fA = __half22float2(hA);
            float2 fB = __half22float2(hB);
            float v0 = t0*fA.x, v1 = t1*fA.y, v2 = t2*fB.x, v3 = t3*fB.y;
            if (n == 0) { m0 = v0; m1 = v1; m2 = v2; m3 = v3; }
            else {
                m0 = fmaxf(m0, v0); m1 = fmaxf(m1, v1);
                m2 = fmaxf(m2, v2); m3 = fmaxf(m3, v3);
            }
        }
        acc0 += m0; acc1 += m1; acc2 += m2; acc3 += m3;
    }
    float4* o = (float4*)&out[(((size_t)d*2048 + p)*12) + rg*4];
    *o = make_float4(acc0, acc1, acc2, acc3);
}

// ---------------- host-side icosa constants --------------------------------
static float h_ico[189];
static bool h_ico_ready = false;

static void compute_icosa_host() {
    const double phi = (1.0 + sqrt(5.0)) * 0.5;
    double v[12][3];
    int idx = 0;
    double as_[2] = {1.0, -1.0};
    double bs_[2] = {phi, -phi};
    for (int ia = 0; ia < 2; ia++)
        for (int ib = 0; ib < 2; ib++) {
            double a = as_[ia], b = bs_[ib];
            v[idx][0] = 0.0; v[idx][1] = a;   v[idx][2] = b;   idx++;
            v[idx][0] = a;   v[idx][1] = b;   v[idx][2] = 0.0; idx++;
            v[idx][0] = b;   v[idx][1] = 0.0; v[idx][2] = a;   idx++;
        }
    for (int i = 0; i < 12; i++) {
        double n = sqrt(v[i][0]*v[i][0] + v[i][1]*v[i][1] + v[i][2]*v[i][2]);
        for (int j = 0; j < 3; j++) { v[i][j] /= n; h_ico[VS_OFF + i*3+j] = (float)v[i][j]; }
    }
    for (int m = 0; m < 5; m++) {
        double t = 2.0 * M_PI * (double)m / 5.0;
        double ct = cos(t), st = sin(t);
        double R[3][3] = {{ct, -st, 0.0}, {st, ct, 0.0}, {0.0, 0.0, 1.0}};
        for (int i = 0; i < 3; i++)
            for (int j = 0; j < 3; j++)
                h_ico[SYMR_OFF + m*9 + i*3 + j] = (float)R[i][j];
    }
    for (int r = 0; r < 12; r++) {
        double c = v[r][2];
        double axx = -v[r][1], axy = v[r][0];       // cross(z, u)
        double s = sqrt(axx*axx + axy*axy);
        double R[3][3];
        if (s < 1e-9) {
            for (int i = 0; i < 3; i++) for (int j = 0; j < 3; j++) R[i][j] = 0.0;
            R[0][0] = 1.0;
            R[1][1] = (c > 0) ? 1.0 : -1.0;
            R[2][2] = (c > 0) ? 1.0 : -1.0;
        } else {
            double kx = axx / s, ky = axy / s;
            double K[3][3] = {{0, 0, ky}, {0, 0, -kx}, {-ky, kx, 0}};
            double KK[3][3];
            for (int i = 0; i < 3; i++)
                for (int j = 0; j < 3; j++) {
                    double acc = 0.0;
                    for (int q = 0; q < 3; q++) acc += K[i][q]*K[q][j];
                    KK[i][j] = acc;
                }
            for (int i = 0; i < 3; i++)
                for (int j = 0; j < 3; j++)
                    R[i][j] = (i == j ? 1.0 : 0.0) + s*K[i][j] + (1.0 - c)*KK[i][j];
        }
        for (int i = 0; i < 3; i++)
            for (int j = 0; j < 3; j++)
                h_ico[VER_OFF + r*9 + i*3 + j] = (float)R[i][j];
    }
}

// ---------------- launch ----------------------------------------------------
extern "C" void kernel_launch(void* const* d_in, const int* in_sizes, int n_in,
                              void* d_out, int out_size) {
    const int*   nbr   = (const int*)d_in[0];   // (1,2048,10)
    const float* verts = (const float*)d_in[1]; // (1,2048,3)
    const float* fmap  = (const float*)d_in[2]; // (1,32,2048,12)
    const float* W     = (const float*)d_in[3]; // (32,32,9)
    const float* bias  = (const float*)d_in[4]; // (32,5)
    const float* dirs  = (const float*)d_in[5]; // (32,2,3)
    const float* fcw   = (const float*)d_in[6]; // (32,32)
    float* out    = (float*)d_out;              // (1,32,2048,12)
    float* fm_out = out + 32*2048*12;           // (1,32,2048,3)

    if (!h_ico_ready) { compute_icosa_host(); h_ico_ready = true; }
    cudaMemcpyToSymbolAsync(g_ICO, h_ico, sizeof(h_ico), 0,
                            cudaMemcpyHostToDevice, 0);

    k_init_weights<<<72, 256>>>(W, bias, dirs);
    k_fm<<<256, 256>>>(fmap, fcw, fm_out);
    k_ka<<<dim3(26, 64), 128>>>();
    k_final<<<512, 384>>>(nbr, verts, out);
}